// round 9
// baseline (speedup 1.0000x reference)
#include <cuda_runtime.h>
#include <cuda_bf16.h>
#include <stdint.h>
#include <math.h>

// ---------------------------------------------------------------------------
// Problem constants
// ---------------------------------------------------------------------------
#define BATCH 2
#define T_IN  2048
#define L_OUT 4096
#define C     512

// Conv tile: M=256 tokens x N=64 cout per CTA, K chunked 4 x 128, 512 threads
#define MTILE 256
#define NTILE 64
#define HALO  3
#define AROWS (MTILE + 2 * HALO)   // 262
#define KCH   128
#define NCH   (C / KCH)            // 4
#define ASTR  272                  // 128 bf16 = 256B + 16 pad

#define A_BUF (AROWS * ASTR)               // 71264
#define B_BUF (NTILE * ASTR)               // 17408
#define SM_A0 0
#define SM_A1 A_BUF
#define SM_B0 (2 * A_BUF)                  // 142528
#define SM_B1 (2 * A_BUF + B_BUF)         // 159936
#define SM_AS (2 * A_BUF + 2 * B_BUF)     // 177344
#define SMEM_TOTAL (SM_AS + AROWS * 4 + 16)  // 178408

// ---------------------------------------------------------------------------
// Device scratch (static __device__ arrays: allocation-free)
// ---------------------------------------------------------------------------
__device__ __nv_bfloat16 g_qx [BATCH * T_IN  * C];
__device__ float         g_asx[BATCH * T_IN];
__device__ float         g_h  [BATCH * L_OUT * C];
__device__ __nv_bfloat16 g_qh [BATCH * L_OUT * C];
__device__ float         g_ash[BATCH * L_OUT];
__device__ float         g_r  [BATCH * L_OUT * C];
__device__ __nv_bfloat16 g_qr [BATCH * L_OUT * C];
__device__ float         g_asr[BATCH * L_OUT];
__device__ float         g_hs [BATCH * L_OUT * C];
__device__ __nv_bfloat16 g_wu [4 * C * C];
__device__ __nv_bfloat16 g_w1 [7 * C * C];
__device__ __nv_bfloat16 g_w2 [7 * C * C];
__device__ float         g_ws [3];
__device__ float         g_part[3 * 256];

// ---------------------------------------------------------------------------
// Weight absmean reductions
// ---------------------------------------------------------------------------
__global__ void absmean_part_all(const float* __restrict__ w0,
                                 const float* __restrict__ w1,
                                 const float* __restrict__ w2,
                                 float* __restrict__ part) {
    const float* w = (blockIdx.y == 0) ? w0 : (blockIdx.y == 1 ? w1 : w2);
    int n = (blockIdx.y == 0) ? 4 * C * C : 7 * C * C;
    __shared__ float sm[256];
    float s = 0.f;
    for (int i = blockIdx.x * 256 + threadIdx.x; i < n; i += 256 * 256)
        s += fabsf(w[i]);
    sm[threadIdx.x] = s;
    __syncthreads();
    for (int st = 128; st > 0; st >>= 1) {
        if (threadIdx.x < st) sm[threadIdx.x] += sm[threadIdx.x + st];
        __syncthreads();
    }
    if (threadIdx.x == 0) part[blockIdx.y * 256 + blockIdx.x] = sm[0];
}

__global__ void absmean_fin_all(const float* __restrict__ part, float* __restrict__ ws_out) {
    int y = blockIdx.x;
    int n_elems = (y == 0) ? 4 * C * C : 7 * C * C;
    __shared__ float sm[256];
    sm[threadIdx.x] = part[y * 256 + threadIdx.x];
    __syncthreads();
    for (int st = 128; st > 0; st >>= 1) {
        if (threadIdx.x < st) sm[threadIdx.x] += sm[threadIdx.x + st];
        __syncthreads();
    }
    if (threadIdx.x == 0) {
        float mean = sm[0] / (float)n_elems;
        ws_out[y] = fmaxf(mean, 1e-5f);
    }
}

// ---------------------------------------------------------------------------
// Ternarize + repack weights to bf16 [k][co][ci]
// ---------------------------------------------------------------------------
__global__ void pack_up_k(const float* __restrict__ w, const float* __restrict__ wsp,
                          __nv_bfloat16* __restrict__ out) {
    int ci = blockIdx.x, co = threadIdx.x;             // w_up: (CIN, COUT, 4)
    float inv = 1.0f / wsp[0];
    const float* src = w + ((size_t)ci * C + co) * 4;
#pragma unroll
    for (int k = 0; k < 4; k++) {
        float q = rintf(src[k] * inv);
        q = fminf(1.f, fmaxf(-1.f, q));
        out[(size_t)k * C * C + (size_t)co * C + ci] = __float2bfloat16_rn(q);
    }
}

__global__ void pack_r_both_k(const float* __restrict__ wa, const float* __restrict__ wb,
                              const float* __restrict__ wsp,
                              __nv_bfloat16* __restrict__ oa, __nv_bfloat16* __restrict__ ob) {
    int co = blockIdx.x, ci = threadIdx.x;             // w_r: (COUT, CIN, 7)
    const float* w = blockIdx.y ? wb : wa;
    __nv_bfloat16* o = blockIdx.y ? ob : oa;
    float inv = 1.0f / wsp[1 + blockIdx.y];
    const float* src = w + ((size_t)co * C + ci) * 7;
#pragma unroll
    for (int k = 0; k < 7; k++) {
        float q = rintf(src[k] * inv);
        q = fminf(1.f, fmaxf(-1.f, q));
        o[(size_t)k * C * C + (size_t)co * C + ci] = __float2bfloat16_rn(q);
    }
}

// ---------------------------------------------------------------------------
// Per-token act_quant: warp per row of 512 floats -> bf16 integer q + scale
// ---------------------------------------------------------------------------
__global__ void act_quant_k(const float* __restrict__ X, __nv_bfloat16* __restrict__ Q,
                            float* __restrict__ S, int rows) {
    int w    = (blockIdx.x * blockDim.x + threadIdx.x) >> 5;
    int lane = threadIdx.x & 31;
    if (w >= rows) return;
    const float4* xr = (const float4*)(X + (size_t)w * C);
    float4 v[4];
    float m = 0.f;
#pragma unroll
    for (int qq = 0; qq < 4; qq++) {
        v[qq] = xr[lane + 32 * qq];
        m = fmaxf(m, fmaxf(fmaxf(fabsf(v[qq].x), fabsf(v[qq].y)),
                           fmaxf(fabsf(v[qq].z), fabsf(v[qq].w))));
    }
#pragma unroll
    for (int o = 16; o; o >>= 1) m = fmaxf(m, __shfl_xor_sync(0xffffffffu, m, o));
    m = fmaxf(m, 1e-5f);
    float scale = 127.0f / m;
    if (lane == 0) S[w] = m / 127.0f;
    __nv_bfloat162* qr = (__nv_bfloat162*)(Q + (size_t)w * C);
#pragma unroll
    for (int qq = 0; qq < 4; qq++) {
        float q0 = fminf(127.f, fmaxf(-128.f, rintf(v[qq].x * scale)));
        float q1 = fminf(127.f, fmaxf(-128.f, rintf(v[qq].y * scale)));
        float q2 = fminf(127.f, fmaxf(-128.f, rintf(v[qq].z * scale)));
        float q3 = fminf(127.f, fmaxf(-128.f, rintf(v[qq].w * scale)));
        int p = lane + 32 * qq;
        qr[2 * p]     = __floats2bfloat162_rn(q0, q1);
        qr[2 * p + 1] = __floats2bfloat162_rn(q2, q3);
    }
}

// ---------------------------------------------------------------------------
// bf16 HMMA conv, cp.async double-buffered pipeline
// ---------------------------------------------------------------------------
struct TapSpec {
    int widx[7];
    int dt[7];
    int n;
};

__device__ __forceinline__ void ldsm4(uint32_t r[4], uint32_t addr) {
    asm volatile("ldmatrix.sync.aligned.m8n8.x4.shared.b16 {%0,%1,%2,%3}, [%4];"
                 : "=r"(r[0]), "=r"(r[1]), "=r"(r[2]), "=r"(r[3]) : "r"(addr));
}

__device__ __forceinline__ void mma_bf16(float c[4], const uint32_t a[4],
                                         uint32_t b0, uint32_t b1) {
    asm volatile(
        "mma.sync.aligned.m16n8k16.row.col.f32.bf16.bf16.f32 "
        "{%0,%1,%2,%3}, {%4,%5,%6,%7}, {%8,%9}, {%0,%1,%2,%3};\n"
        : "+f"(c[0]), "+f"(c[1]), "+f"(c[2]), "+f"(c[3])
        : "r"(a[0]), "r"(a[1]), "r"(a[2]), "r"(a[3]), "r"(b0), "r"(b1));
}

__device__ __forceinline__ void cpa16(uint32_t dst, const void* src, int sz) {
    asm volatile("cp.async.cg.shared.global [%0], [%1], 16, %2;"
                 :: "r"(dst), "l"(src), "r"(sz));
}
__device__ __forceinline__ void cpa_commit() {
    asm volatile("cp.async.commit_group;" ::: "memory");
}
__device__ __forceinline__ void cpa_wait1() {
    asm volatile("cp.async.wait_group 1;" ::: "memory");
}
__device__ __forceinline__ void cpa_wait0() {
    asm volatile("cp.async.wait_group 0;" ::: "memory");
}

__global__ void __launch_bounds__(512, 1)
conv_mma_kernel(const __nv_bfloat16* __restrict__ Aq, const float* __restrict__ As,
                int Tin,
                const __nv_bfloat16* __restrict__ Wq, const float* __restrict__ wsp,
                const float* __restrict__ bias, const float* __restrict__ resid,
                float* __restrict__ Y, int out_mul, int nphase,
                TapSpec taps0, TapSpec taps1, int do_silu) {
    extern __shared__ char smem[];
    float* sAs = (float*)(smem + SM_AS);
    const uint32_t smu = (uint32_t)__cvta_generic_to_shared(smem);

    const int b   = blockIdx.z;
    const int t0  = blockIdx.x * MTILE;
    const int co0 = blockIdx.y * NTILE;
    const __nv_bfloat16* Ab = Aq + (size_t)b * Tin * C;
    const float* Asb = As + (size_t)b * Tin;
    float* Yb = Y + (size_t)b * L_OUT * C;
    const float* Rb = resid ? resid + (size_t)b * L_OUT * C : nullptr;

    const int tid = threadIdx.x;
    // Stage act scales once (cover all taps' halo range)
    for (int i = tid; i < AROWS; i += 512) {
        int t = t0 - HALO + i;
        sAs[i] = (t >= 0 && t < Tin) ? Asb[t] : 0.0f;
    }
    __syncthreads();

    const int lane = tid & 31, warp = tid >> 5;
    const int gid = lane >> 2, tg = lane & 3;
    const int wm = warp & 7, wn = warp >> 3;   // 8 m-slices x 2 n-halves
    const float ws = *wsp;

    const uint32_t aRowSel = (uint32_t)(lane & 15);
    const uint32_t aColSel = (uint32_t)((lane >> 4) << 4);
    const uint32_t bRowSel = (uint32_t)(((lane >> 4) << 3) + (lane & 7));
    const uint32_t bColSel = (uint32_t)(((lane >> 3) & 1) << 4);

    for (int p = 0; p < nphase; p++) {
        const TapSpec& tp = (p == 0) ? taps0 : taps1;
        const int ntaps = tp.n;
        const int NU = ntaps * NCH;

        float facc[2][4][4];
#pragma unroll
        for (int i = 0; i < 2; i++)
#pragma unroll
            for (int j = 0; j < 4; j++)
#pragma unroll
                for (int e = 0; e < 4; e++) facc[i][j][e] = 0.f;

        // --- pipeline unit issue: unit u = (chunk c = u/ntaps, tap t = u%ntaps)
        auto issue_unit = [&](int u) {
            int c = u / ntaps;
            int t = u - c * ntaps;
            int ci0 = c * KCH;
            // B tile: 64 rows x 128 ci (1024 x 16B)
            const __nv_bfloat16* W =
                Wq + (size_t)tp.widx[t] * C * C + (size_t)co0 * C + ci0;
            uint32_t bbase = smu + ((u & 1) ? SM_B1 : SM_B0);
            for (int idx = tid; idx < NTILE * 16; idx += 512) {
                int r = idx >> 4, cc = idx & 15;
                cpa16(bbase + r * ASTR + cc * 16, W + (size_t)r * C + cc * 8, 16);
            }
            // A chunk on first tap of each chunk: 262 rows x 128 ci
            if (t == 0) {
                uint32_t abase = smu + ((c & 1) ? SM_A1 : SM_A0);
                for (int idx = tid; idx < AROWS * 16; idx += 512) {
                    int r = idx >> 4, cc = idx & 15;
                    int tr = t0 - HALO + r;
                    int ok = (tr >= 0 && tr < Tin) ? 16 : 0;
                    cpa16(abase + r * ASTR + cc * 16,
                          Ab + (size_t)tr * C + ci0 + cc * 8, ok);
                }
            }
            cpa_commit();
        };

        issue_unit(0);
        for (int u = 0; u < NU; u++) {
            const int c = u / ntaps;
            const int t = u - c * ntaps;
            if (u + 1 < NU) { issue_unit(u + 1); cpa_wait1(); }
            else           { cpa_wait0(); }
            __syncthreads();   // unit u visible to all warps

            const int dt = tp.dt[t];
            const int arow0 = wm * 32 + HALO + dt;
            const uint32_t aBase = smu + ((c & 1) ? SM_A1 : SM_A0)
                                 + (uint32_t)(arow0 + aRowSel) * ASTR + aColSel;
            const uint32_t bBase = smu + ((u & 1) ? SM_B1 : SM_B0)
                                 + (uint32_t)(wn * 32 + bRowSel) * ASTR + bColSel;

            float cacc[2][4][4];
#pragma unroll
            for (int i = 0; i < 2; i++)
#pragma unroll
                for (int j = 0; j < 4; j++)
#pragma unroll
                    for (int e = 0; e < 4; e++) cacc[i][j][e] = 0.f;

#pragma unroll
            for (int kk = 0; kk < 8; kk++) {
                const uint32_t col = kk * 32;   // k16 = 32B
                uint32_t a0[4], a1[4], bv0[4], bv1[4];
                ldsm4(a0, aBase + col);
                ldsm4(a1, aBase + 16 * ASTR + col);
                ldsm4(bv0, bBase + col);
                ldsm4(bv1, bBase + 16 * ASTR + col);
                mma_bf16(cacc[0][0], a0, bv0[0], bv0[1]);
                mma_bf16(cacc[0][1], a0, bv0[2], bv0[3]);
                mma_bf16(cacc[0][2], a0, bv1[0], bv1[1]);
                mma_bf16(cacc[0][3], a0, bv1[2], bv1[3]);
                mma_bf16(cacc[1][0], a1, bv0[0], bv0[1]);
                mma_bf16(cacc[1][1], a1, bv0[2], bv0[3]);
                mma_bf16(cacc[1][2], a1, bv1[0], bv1[1]);
                mma_bf16(cacc[1][3], a1, bv1[2], bv1[3]);
            }

            // per-token rescale (exact per chunk: s*(P0+..) = sum of s*Pc)
#pragma unroll
            for (int i = 0; i < 2; i++) {
                float as_lo = sAs[arow0 + i * 16 + gid];
                float as_hi = sAs[arow0 + i * 16 + gid + 8];
#pragma unroll
                for (int j = 0; j < 4; j++) {
                    facc[i][j][0] += cacc[i][j][0] * as_lo;
                    facc[i][j][1] += cacc[i][j][1] * as_lo;
                    facc[i][j][2] += cacc[i][j][2] * as_hi;
                    facc[i][j][3] += cacc[i][j][3] * as_hi;
                }
            }
            __syncthreads();   // all warps done reading before next overwrite
        }

        // Epilogue for this phase
        const int out_add = (nphase == 2) ? p : 0;
#pragma unroll
        for (int i = 0; i < 2; i++) {
            int m0 = t0 + wm * 32 + i * 16 + gid;
#pragma unroll
            for (int j = 0; j < 4; j++) {
                int co = co0 + wn * 32 + j * 8 + tg * 2;
                float b0 = bias[co], b1 = bias[co + 1];
                float y0 = facc[i][j][0] * ws + b0;
                float y1 = facc[i][j][1] * ws + b1;
                float y2 = facc[i][j][2] * ws + b0;
                float y3 = facc[i][j][3] * ws + b1;
                if (do_silu) {
                    y0 = y0 / (1.f + __expf(-y0));
                    y1 = y1 / (1.f + __expf(-y1));
                    y2 = y2 / (1.f + __expf(-y2));
                    y3 = y3 / (1.f + __expf(-y3));
                }
                int l_lo = m0 * out_mul + out_add;
                int l_hi = (m0 + 8) * out_mul + out_add;
                size_t i_lo = (size_t)l_lo * C + co;
                size_t i_hi = (size_t)l_hi * C + co;
                if (Rb) {
                    float2 r0 = *(const float2*)(Rb + i_lo);
                    float2 r1 = *(const float2*)(Rb + i_hi);
                    y0 += r0.x; y1 += r0.y; y2 += r1.x; y3 += r1.y;
                }
                *(float2*)(Yb + i_lo) = make_float2(y0, y1);
                *(float2*)(Yb + i_hi) = make_float2(y2, y3);
            }
        }
    }
}

// ---------------------------------------------------------------------------
// LayerNorm over channels (warp per row)
// ---------------------------------------------------------------------------
__global__ void ln_k(const float* __restrict__ H, const float* __restrict__ lw,
                     const float* __restrict__ lb, float* __restrict__ O) {
    int w    = (blockIdx.x * blockDim.x + threadIdx.x) >> 5;
    int lane = threadIdx.x & 31;
    if (w >= BATCH * L_OUT) return;
    const float4* hr = (const float4*)(H + (size_t)w * C);
    float4 v[4];
    float s = 0.f;
#pragma unroll
    for (int qq = 0; qq < 4; qq++) {
        v[qq] = hr[lane + 32 * qq];
        s += v[qq].x + v[qq].y + v[qq].z + v[qq].w;
    }
#pragma unroll
    for (int o = 16; o; o >>= 1) s += __shfl_xor_sync(0xffffffffu, s, o);
    float mu = s / (float)C;
    float vs = 0.f;
#pragma unroll
    for (int qq = 0; qq < 4; qq++) {
        float dx = v[qq].x - mu, dy = v[qq].y - mu, dz = v[qq].z - mu, dw = v[qq].w - mu;
        vs += dx * dx + dy * dy + dz * dz + dw * dw;
    }
#pragma unroll
    for (int o = 16; o; o >>= 1) vs += __shfl_xor_sync(0xffffffffu, vs, o);
    float inv = rsqrtf(vs / (float)C + 1e-5f);
    const float4* lwv = (const float4*)lw;
    const float4* lbv = (const float4*)lb;
    float4* ov = (float4*)(O + (size_t)w * C);
#pragma unroll
    for (int qq = 0; qq < 4; qq++) {
        float4 wv = lwv[lane + 32 * qq];
        float4 bv = lbv[lane + 32 * qq];
        float4 o4;
        o4.x = (v[qq].x - mu) * inv * wv.x + bv.x;
        o4.y = (v[qq].y - mu) * inv * wv.y + bv.y;
        o4.z = (v[qq].z - mu) * inv * wv.z + bv.z;
        o4.w = (v[qq].w - mu) * inv * wv.w + bv.w;
        ov[lane + 32 * qq] = o4;
    }
}

// ---------------------------------------------------------------------------
// Launch
// ---------------------------------------------------------------------------
extern "C" void kernel_launch(void* const* d_in, const int* in_sizes, int n_in,
                              void* d_out, int out_size) {
    const float* x    = (const float*)d_in[0];
    const float* w_up = (const float*)d_in[1];
    const float* b_up = (const float*)d_in[2];
    const float* w_r1 = (const float*)d_in[3];
    const float* b_r1 = (const float*)d_in[4];
    const float* w_r2 = (const float*)d_in[5];
    const float* b_r2 = (const float*)d_in[6];
    const float* ln_w = (const float*)d_in[7];
    const float* ln_b = (const float*)d_in[8];
    float* out = (float*)d_out;

    __nv_bfloat16 *qx, *qh, *qr, *wu, *w1, *w2;
    float *asx, *ash, *asr, *h, *r, *hs, *ws, *part;
    cudaGetSymbolAddress((void**)&qx,  g_qx);
    cudaGetSymbolAddress((void**)&qh,  g_qh);
    cudaGetSymbolAddress((void**)&qr,  g_qr);
    cudaGetSymbolAddress((void**)&wu,  g_wu);
    cudaGetSymbolAddress((void**)&w1,  g_w1);
    cudaGetSymbolAddress((void**)&w2,  g_w2);
    cudaGetSymbolAddress((void**)&asx, g_asx);
    cudaGetSymbolAddress((void**)&ash, g_ash);
    cudaGetSymbolAddress((void**)&asr, g_asr);
    cudaGetSymbolAddress((void**)&h,   g_h);
    cudaGetSymbolAddress((void**)&r,   g_r);
    cudaGetSymbolAddress((void**)&hs,  g_hs);
    cudaGetSymbolAddress((void**)&ws,  g_ws);
    cudaGetSymbolAddress((void**)&part, g_part);

    cudaFuncSetAttribute((const void*)conv_mma_kernel,
                         cudaFuncAttributeMaxDynamicSharedMemorySize, SMEM_TOTAL);

    TapSpec te; te.n = 2;                 // even outputs l=2t: k=1 @ t, k=3 @ t-1
    te.widx[0] = 1; te.dt[0] = 0;
    te.widx[1] = 3; te.dt[1] = -1;
    for (int k = 2; k < 7; k++) { te.widx[k] = 0; te.dt[k] = 0; }
    TapSpec to; to.n = 2;                 // odd outputs l=2t+1: k=0 @ t+1, k=2 @ t
    to.widx[0] = 0; to.dt[0] = 1;
    to.widx[1] = 2; to.dt[1] = 0;
    for (int k = 2; k < 7; k++) { to.widx[k] = 0; to.dt[k] = 0; }
    TapSpec t7; t7.n = 7;
    for (int k = 0; k < 7; k++) { t7.widx[k] = k; t7.dt[k] = k - 3; }
    TapSpec tz; tz.n = 1;
    for (int k = 0; k < 7; k++) { tz.widx[k] = 0; tz.dt[k] = 0; }

    // 1: weight absmean partials
    absmean_part_all<<<dim3(256, 3), 256>>>(w_up, w_r1, w_r2, part);
    // 2: finalize scales
    absmean_fin_all<<<3, 256>>>(part, ws);
    // 3: pack upsample weight -> bf16 [k][co][ci]
    pack_up_k<<<C, C>>>(w_up, ws, wu);
    // 4: pack both refine weights
    pack_r_both_k<<<dim3(C, 2), C>>>(w_r1, w_r2, ws, w1, w2);
    // 5: act-quant input x (token-major (B,T,CIN))
    act_quant_k<<<BATCH * T_IN / 8, 256>>>(x, qx, asx, BATCH * T_IN);
    // 6: fused transposed conv (even+odd phases), pipelined HMMA
    conv_mma_kernel<<<dim3(T_IN / MTILE, C / NTILE, BATCH), 512, SMEM_TOTAL>>>(
        qx, asx, T_IN, wu, ws, b_up, nullptr, h, 2, 2, te, to, 0);
    // 7: quantize h
    act_quant_k<<<BATCH * L_OUT / 8, 256>>>(h, qh, ash, BATCH * L_OUT);
    // 8: refine conv 1 (+SiLU)
    conv_mma_kernel<<<dim3(L_OUT / MTILE, C / NTILE, BATCH), 512, SMEM_TOTAL>>>(
        qh, ash, L_OUT, w1, ws + 1, b_r1, nullptr, r, 1, 1, t7, tz, 1);
    // 9: quantize silu(r)
    act_quant_k<<<BATCH * L_OUT / 8, 256>>>(r, qr, asr, BATCH * L_OUT);
    // 10: refine conv 2 (+residual h)
    conv_mma_kernel<<<dim3(L_OUT / MTILE, C / NTILE, BATCH), 512, SMEM_TOTAL>>>(
        qr, asr, L_OUT, w2, ws + 2, b_r2, h, hs, 1, 1, t7, tz, 0);
    // 11: LayerNorm -> output (B, L, Cout) fp32
    ln_k<<<BATCH * L_OUT / 8, 256>>>(hs, ln_w, ln_b, out);
}

// round 10
// speedup vs baseline: 1.0815x; 1.0815x over previous
#include <cuda_runtime.h>
#include <cuda_bf16.h>
#include <stdint.h>
#include <math.h>

// ---------------------------------------------------------------------------
// Problem constants
// ---------------------------------------------------------------------------
#define BATCH 2
#define T_IN  2048
#define L_OUT 4096
#define C     512

// Conv tile: M=128 x N=64 per CTA, 256 threads, K chunked 4 x 128, occ 2
#define MTILE 128
#define NTILE 64
#define HALO  3
#define AROWS (MTILE + 2 * HALO)   // 134
#define KCH   128
#define NCH   (C / KCH)            // 4
#define ASTR  272                  // 128 bf16 = 256B + 16 pad

#define A_BUF (AROWS * ASTR)                 // 36448
#define B_BUF (NTILE * ASTR)                 // 17408
#define SM_A0 0
#define SM_A1 A_BUF
#define SM_B0 (2 * A_BUF)                    // 72896
#define SM_B1 (2 * A_BUF + B_BUF)            // 90304
#define SM_AS (2 * A_BUF + 2 * B_BUF)        // 107712
#define SMEM_TOTAL (SM_AS + AROWS * 4 + 8)   // 108256 (x2 = 216.5KB <= 227KB)

// ---------------------------------------------------------------------------
// Device scratch (static __device__ arrays: allocation-free)
// ---------------------------------------------------------------------------
__device__ __nv_bfloat16 g_qx [BATCH * T_IN  * C];
__device__ float         g_asx[BATCH * T_IN];
__device__ float         g_h  [BATCH * L_OUT * C];
__device__ __nv_bfloat16 g_qh [BATCH * L_OUT * C];
__device__ float         g_ash[BATCH * L_OUT];
__device__ float         g_r  [BATCH * L_OUT * C];
__device__ __nv_bfloat16 g_qr [BATCH * L_OUT * C];
__device__ float         g_asr[BATCH * L_OUT];
__device__ float         g_hs [BATCH * L_OUT * C];
__device__ __nv_bfloat16 g_wu [4 * C * C];
__device__ __nv_bfloat16 g_w1 [7 * C * C];
__device__ __nv_bfloat16 g_w2 [7 * C * C];
__device__ float         g_ws [3];
__device__ float         g_part[3 * 256];

// ---------------------------------------------------------------------------
// Weight absmean reductions
// ---------------------------------------------------------------------------
__global__ void absmean_part_all(const float* __restrict__ w0,
                                 const float* __restrict__ w1,
                                 const float* __restrict__ w2,
                                 float* __restrict__ part) {
    const float* w = (blockIdx.y == 0) ? w0 : (blockIdx.y == 1 ? w1 : w2);
    int n = (blockIdx.y == 0) ? 4 * C * C : 7 * C * C;
    __shared__ float sm[256];
    float s = 0.f;
    for (int i = blockIdx.x * 256 + threadIdx.x; i < n; i += 256 * 256)
        s += fabsf(w[i]);
    sm[threadIdx.x] = s;
    __syncthreads();
    for (int st = 128; st > 0; st >>= 1) {
        if (threadIdx.x < st) sm[threadIdx.x] += sm[threadIdx.x + st];
        __syncthreads();
    }
    if (threadIdx.x == 0) part[blockIdx.y * 256 + blockIdx.x] = sm[0];
}

__global__ void absmean_fin_all(const float* __restrict__ part, float* __restrict__ ws_out) {
    int y = blockIdx.x;
    int n_elems = (y == 0) ? 4 * C * C : 7 * C * C;
    __shared__ float sm[256];
    sm[threadIdx.x] = part[y * 256 + threadIdx.x];
    __syncthreads();
    for (int st = 128; st > 0; st >>= 1) {
        if (threadIdx.x < st) sm[threadIdx.x] += sm[threadIdx.x + st];
        __syncthreads();
    }
    if (threadIdx.x == 0) {
        float mean = sm[0] / (float)n_elems;
        ws_out[y] = fmaxf(mean, 1e-5f);
    }
}

// ---------------------------------------------------------------------------
// Ternarize + repack weights to bf16 [k][co][ci]
// ---------------------------------------------------------------------------
__global__ void pack_up_k(const float* __restrict__ w, const float* __restrict__ wsp,
                          __nv_bfloat16* __restrict__ out) {
    int ci = blockIdx.x, co = threadIdx.x;             // w_up: (CIN, COUT, 4)
    float inv = 1.0f / wsp[0];
    const float* src = w + ((size_t)ci * C + co) * 4;
#pragma unroll
    for (int k = 0; k < 4; k++) {
        float q = rintf(src[k] * inv);
        q = fminf(1.f, fmaxf(-1.f, q));
        out[(size_t)k * C * C + (size_t)co * C + ci] = __float2bfloat16_rn(q);
    }
}

__global__ void pack_r_both_k(const float* __restrict__ wa, const float* __restrict__ wb,
                              const float* __restrict__ wsp,
                              __nv_bfloat16* __restrict__ oa, __nv_bfloat16* __restrict__ ob) {
    int co = blockIdx.x, ci = threadIdx.x;             // w_r: (COUT, CIN, 7)
    const float* w = blockIdx.y ? wb : wa;
    __nv_bfloat16* o = blockIdx.y ? ob : oa;
    float inv = 1.0f / wsp[1 + blockIdx.y];
    const float* src = w + ((size_t)co * C + ci) * 7;
#pragma unroll
    for (int k = 0; k < 7; k++) {
        float q = rintf(src[k] * inv);
        q = fminf(1.f, fmaxf(-1.f, q));
        o[(size_t)k * C * C + (size_t)co * C + ci] = __float2bfloat16_rn(q);
    }
}

// ---------------------------------------------------------------------------
// Per-token act_quant: warp per row of 512 floats -> bf16 integer q + scale
// ---------------------------------------------------------------------------
__global__ void act_quant_k(const float* __restrict__ X, __nv_bfloat16* __restrict__ Q,
                            float* __restrict__ S, int rows) {
    int w    = (blockIdx.x * blockDim.x + threadIdx.x) >> 5;
    int lane = threadIdx.x & 31;
    if (w >= rows) return;
    const float4* xr = (const float4*)(X + (size_t)w * C);
    float4 v[4];
    float m = 0.f;
#pragma unroll
    for (int qq = 0; qq < 4; qq++) {
        v[qq] = xr[lane + 32 * qq];
        m = fmaxf(m, fmaxf(fmaxf(fabsf(v[qq].x), fabsf(v[qq].y)),
                           fmaxf(fabsf(v[qq].z), fabsf(v[qq].w))));
    }
#pragma unroll
    for (int o = 16; o; o >>= 1) m = fmaxf(m, __shfl_xor_sync(0xffffffffu, m, o));
    m = fmaxf(m, 1e-5f);
    float scale = 127.0f / m;
    if (lane == 0) S[w] = m / 127.0f;
    __nv_bfloat162* qr = (__nv_bfloat162*)(Q + (size_t)w * C);
#pragma unroll
    for (int qq = 0; qq < 4; qq++) {
        float q0 = fminf(127.f, fmaxf(-128.f, rintf(v[qq].x * scale)));
        float q1 = fminf(127.f, fmaxf(-128.f, rintf(v[qq].y * scale)));
        float q2 = fminf(127.f, fmaxf(-128.f, rintf(v[qq].z * scale)));
        float q3 = fminf(127.f, fmaxf(-128.f, rintf(v[qq].w * scale)));
        int p = lane + 32 * qq;
        qr[2 * p]     = __floats2bfloat162_rn(q0, q1);
        qr[2 * p + 1] = __floats2bfloat162_rn(q2, q3);
    }
}

// ---------------------------------------------------------------------------
// bf16 HMMA conv, cp.async double-buffered FIFO, occ-2 config
// ---------------------------------------------------------------------------
struct TapSpec {
    int widx[7];
    int dt[7];
    int n;
};

__device__ __forceinline__ void ldsm4(uint32_t r[4], uint32_t addr) {
    asm volatile("ldmatrix.sync.aligned.m8n8.x4.shared.b16 {%0,%1,%2,%3}, [%4];"
                 : "=r"(r[0]), "=r"(r[1]), "=r"(r[2]), "=r"(r[3]) : "r"(addr));
}

__device__ __forceinline__ void mma_bf16(float c[4], const uint32_t a[4],
                                         uint32_t b0, uint32_t b1) {
    asm volatile(
        "mma.sync.aligned.m16n8k16.row.col.f32.bf16.bf16.f32 "
        "{%0,%1,%2,%3}, {%4,%5,%6,%7}, {%8,%9}, {%0,%1,%2,%3};\n"
        : "+f"(c[0]), "+f"(c[1]), "+f"(c[2]), "+f"(c[3])
        : "r"(a[0]), "r"(a[1]), "r"(a[2]), "r"(a[3]), "r"(b0), "r"(b1));
}

__device__ __forceinline__ void cpa16(uint32_t dst, const void* src, int sz) {
    asm volatile("cp.async.cg.shared.global [%0], [%1], 16, %2;"
                 :: "r"(dst), "l"(src), "r"(sz));
}
__device__ __forceinline__ void cpa_commit() {
    asm volatile("cp.async.commit_group;" ::: "memory");
}
__device__ __forceinline__ void cpa_wait1() {
    asm volatile("cp.async.wait_group 1;" ::: "memory");
}
__device__ __forceinline__ void cpa_wait0() {
    asm volatile("cp.async.wait_group 0;" ::: "memory");
}

__global__ void __launch_bounds__(256, 2)
conv_mma_kernel(const __nv_bfloat16* __restrict__ Aq, const float* __restrict__ As,
                int Tin,
                const __nv_bfloat16* __restrict__ Wq, const float* __restrict__ wsp,
                const float* __restrict__ bias, const float* __restrict__ resid,
                float* __restrict__ Y, int out_mul, int nphase,
                TapSpec taps0, TapSpec taps1, int do_silu) {
    extern __shared__ char smem[];
    float* sAs = (float*)(smem + SM_AS);
    const uint32_t smu = (uint32_t)__cvta_generic_to_shared(smem);

    const int b   = blockIdx.z;
    const int t0  = blockIdx.x * MTILE;
    const int co0 = blockIdx.y * NTILE;
    const __nv_bfloat16* Ab = Aq + (size_t)b * Tin * C;
    const float* Asb = As + (size_t)b * Tin;
    float* Yb = Y + (size_t)b * L_OUT * C;
    const float* Rb = resid ? resid + (size_t)b * L_OUT * C : nullptr;

    const int tid = threadIdx.x;
    // Stage act scales once (cover all taps' halo range)
    if (tid < AROWS) {
        int t = t0 - HALO + tid;
        sAs[tid] = (t >= 0 && t < Tin) ? Asb[t] : 0.0f;
    }
    __syncthreads();

    const int lane = tid & 31, warp = tid >> 5;
    const int gid = lane >> 2, tg = lane & 3;
    const int wm = warp & 3, wn = warp >> 2;   // 4 m-slices x 2 n-halves
    const float ws = *wsp;

    const uint32_t aRowSel = (uint32_t)(lane & 15);
    const uint32_t aColSel = (uint32_t)((lane >> 4) << 4);
    const uint32_t bRowSel = (uint32_t)(((lane >> 4) << 3) + (lane & 7));
    const uint32_t bColSel = (uint32_t)(((lane >> 3) & 1) << 4);

    for (int p = 0; p < nphase; p++) {
        const TapSpec& tp = (p == 0) ? taps0 : taps1;
        const int ntaps = tp.n;
        const int NU = ntaps * NCH;

        float facc[2][4][4];
#pragma unroll
        for (int i = 0; i < 2; i++)
#pragma unroll
            for (int j = 0; j < 4; j++)
#pragma unroll
                for (int e = 0; e < 4; e++) facc[i][j][e] = 0.f;

        // pipeline unit u = (chunk c = u/ntaps, tap t = u%ntaps)
        auto issue_unit = [&](int u) {
            int c = u / ntaps;
            int t = u - c * ntaps;
            int ci0 = c * KCH;
            // B tile: 64 rows x 128 ci (256B/row = 16 x 16B)
            const __nv_bfloat16* W =
                Wq + (size_t)tp.widx[t] * C * C + (size_t)co0 * C + ci0;
            uint32_t bbase = smu + ((u & 1) ? SM_B1 : SM_B0);
            for (int idx = tid; idx < NTILE * 16; idx += 256) {
                int r = idx >> 4, cc = idx & 15;
                cpa16(bbase + r * ASTR + cc * 16, W + (size_t)r * C + cc * 8, 16);
            }
            // A chunk on first tap of each chunk: 134 rows x 128 ci
            if (t == 0) {
                uint32_t abase = smu + ((c & 1) ? SM_A1 : SM_A0);
                for (int idx = tid; idx < AROWS * 16; idx += 256) {
                    int r = idx >> 4, cc = idx & 15;
                    int tr = t0 - HALO + r;
                    int ok = (tr >= 0 && tr < Tin) ? 16 : 0;
                    cpa16(abase + r * ASTR + cc * 16,
                          Ab + (size_t)tr * C + ci0 + cc * 8, ok);
                }
            }
            cpa_commit();
        };

        issue_unit(0);
        for (int u = 0; u < NU; u++) {
            const int c = u / ntaps;
            const int t = u - c * ntaps;
            if (u + 1 < NU) { issue_unit(u + 1); cpa_wait1(); }
            else           { cpa_wait0(); }
            __syncthreads();   // unit u visible to all warps

            const int dt = tp.dt[t];
            const int arow0 = wm * 32 + HALO + dt;
            const uint32_t aBase = smu + ((c & 1) ? SM_A1 : SM_A0)
                                 + (uint32_t)(arow0 + aRowSel) * ASTR + aColSel;
            const uint32_t bBase = smu + ((u & 1) ? SM_B1 : SM_B0)
                                 + (uint32_t)(wn * 32 + bRowSel) * ASTR + bColSel;

            float cacc[2][4][4];
#pragma unroll
            for (int i = 0; i < 2; i++)
#pragma unroll
                for (int j = 0; j < 4; j++)
#pragma unroll
                    for (int e = 0; e < 4; e++) cacc[i][j][e] = 0.f;

#pragma unroll
            for (int kk = 0; kk < 8; kk++) {
                const uint32_t col = kk * 32;   // k16 = 32B
                uint32_t a0[4], a1[4], bv0[4], bv1[4];
                ldsm4(a0, aBase + col);
                ldsm4(a1, aBase + 16 * ASTR + col);
                ldsm4(bv0, bBase + col);
                ldsm4(bv1, bBase + 16 * ASTR + col);
                mma_bf16(cacc[0][0], a0, bv0[0], bv0[1]);
                mma_bf16(cacc[0][1], a0, bv0[2], bv0[3]);
                mma_bf16(cacc[0][2], a0, bv1[0], bv1[1]);
                mma_bf16(cacc[0][3], a0, bv1[2], bv1[3]);
                mma_bf16(cacc[1][0], a1, bv0[0], bv0[1]);
                mma_bf16(cacc[1][1], a1, bv0[2], bv0[3]);
                mma_bf16(cacc[1][2], a1, bv1[0], bv1[1]);
                mma_bf16(cacc[1][3], a1, bv1[2], bv1[3]);
            }

            // per-token rescale (exact per chunk: s*(P0+..) = sum of s*Pc)
#pragma unroll
            for (int i = 0; i < 2; i++) {
                float as_lo = sAs[arow0 + i * 16 + gid];
                float as_hi = sAs[arow0 + i * 16 + gid + 8];
#pragma unroll
                for (int j = 0; j < 4; j++) {
                    facc[i][j][0] += cacc[i][j][0] * as_lo;
                    facc[i][j][1] += cacc[i][j][1] * as_lo;
                    facc[i][j][2] += cacc[i][j][2] * as_hi;
                    facc[i][j][3] += cacc[i][j][3] * as_hi;
                }
            }
            __syncthreads();   // all reads done before buffer reuse at u+2
        }

        // Epilogue for this phase
        const int out_add = (nphase == 2) ? p : 0;
#pragma unroll
        for (int i = 0; i < 2; i++) {
            int m0 = t0 + wm * 32 + i * 16 + gid;
#pragma unroll
            for (int j = 0; j < 4; j++) {
                int co = co0 + wn * 32 + j * 8 + tg * 2;
                float b0 = bias[co], b1 = bias[co + 1];
                float y0 = facc[i][j][0] * ws + b0;
                float y1 = facc[i][j][1] * ws + b1;
                float y2 = facc[i][j][2] * ws + b0;
                float y3 = facc[i][j][3] * ws + b1;
                if (do_silu) {
                    y0 = y0 / (1.f + __expf(-y0));
                    y1 = y1 / (1.f + __expf(-y1));
                    y2 = y2 / (1.f + __expf(-y2));
                    y3 = y3 / (1.f + __expf(-y3));
                }
                int l_lo = m0 * out_mul + out_add;
                int l_hi = (m0 + 8) * out_mul + out_add;
                size_t i_lo = (size_t)l_lo * C + co;
                size_t i_hi = (size_t)l_hi * C + co;
                if (Rb) {
                    float2 r0 = *(const float2*)(Rb + i_lo);
                    float2 r1 = *(const float2*)(Rb + i_hi);
                    y0 += r0.x; y1 += r0.y; y2 += r1.x; y3 += r1.y;
                }
                *(float2*)(Yb + i_lo) = make_float2(y0, y1);
                *(float2*)(Yb + i_hi) = make_float2(y2, y3);
            }
        }
    }
}

// ---------------------------------------------------------------------------
// LayerNorm over channels (warp per row)
// ---------------------------------------------------------------------------
__global__ void ln_k(const float* __restrict__ H, const float* __restrict__ lw,
                     const float* __restrict__ lb, float* __restrict__ O) {
    int w    = (blockIdx.x * blockDim.x + threadIdx.x) >> 5;
    int lane = threadIdx.x & 31;
    if (w >= BATCH * L_OUT) return;
    const float4* hr = (const float4*)(H + (size_t)w * C);
    float4 v[4];
    float s = 0.f;
#pragma unroll
    for (int qq = 0; qq < 4; qq++) {
        v[qq] = hr[lane + 32 * qq];
        s += v[qq].x + v[qq].y + v[qq].z + v[qq].w;
    }
#pragma unroll
    for (int o = 16; o; o >>= 1) s += __shfl_xor_sync(0xffffffffu, s, o);
    float mu = s / (float)C;
    float vs = 0.f;
#pragma unroll
    for (int qq = 0; qq < 4; qq++) {
        float dx = v[qq].x - mu, dy = v[qq].y - mu, dz = v[qq].z - mu, dw = v[qq].w - mu;
        vs += dx * dx + dy * dy + dz * dz + dw * dw;
    }
#pragma unroll
    for (int o = 16; o; o >>= 1) vs += __shfl_xor_sync(0xffffffffu, vs, o);
    float inv = rsqrtf(vs / (float)C + 1e-5f);
    const float4* lwv = (const float4*)lw;
    const float4* lbv = (const float4*)lb;
    float4* ov = (float4*)(O + (size_t)w * C);
#pragma unroll
    for (int qq = 0; qq < 4; qq++) {
        float4 wv = lwv[lane + 32 * qq];
        float4 bv = lbv[lane + 32 * qq];
        float4 o4;
        o4.x = (v[qq].x - mu) * inv * wv.x + bv.x;
        o4.y = (v[qq].y - mu) * inv * wv.y + bv.y;
        o4.z = (v[qq].z - mu) * inv * wv.z + bv.z;
        o4.w = (v[qq].w - mu) * inv * wv.w + bv.w;
        ov[lane + 32 * qq] = o4;
    }
}

// ---------------------------------------------------------------------------
// Launch
// ---------------------------------------------------------------------------
extern "C" void kernel_launch(void* const* d_in, const int* in_sizes, int n_in,
                              void* d_out, int out_size) {
    const float* x    = (const float*)d_in[0];
    const float* w_up = (const float*)d_in[1];
    const float* b_up = (const float*)d_in[2];
    const float* w_r1 = (const float*)d_in[3];
    const float* b_r1 = (const float*)d_in[4];
    const float* w_r2 = (const float*)d_in[5];
    const float* b_r2 = (const float*)d_in[6];
    const float* ln_w = (const float*)d_in[7];
    const float* ln_b = (const float*)d_in[8];
    float* out = (float*)d_out;

    __nv_bfloat16 *qx, *qh, *qr, *wu, *w1, *w2;
    float *asx, *ash, *asr, *h, *r, *hs, *ws, *part;
    cudaGetSymbolAddress((void**)&qx,  g_qx);
    cudaGetSymbolAddress((void**)&qh,  g_qh);
    cudaGetSymbolAddress((void**)&qr,  g_qr);
    cudaGetSymbolAddress((void**)&wu,  g_wu);
    cudaGetSymbolAddress((void**)&w1,  g_w1);
    cudaGetSymbolAddress((void**)&w2,  g_w2);
    cudaGetSymbolAddress((void**)&asx, g_asx);
    cudaGetSymbolAddress((void**)&ash, g_ash);
    cudaGetSymbolAddress((void**)&asr, g_asr);
    cudaGetSymbolAddress((void**)&h,   g_h);
    cudaGetSymbolAddress((void**)&r,   g_r);
    cudaGetSymbolAddress((void**)&hs,  g_hs);
    cudaGetSymbolAddress((void**)&ws,  g_ws);
    cudaGetSymbolAddress((void**)&part, g_part);

    cudaFuncSetAttribute((const void*)conv_mma_kernel,
                         cudaFuncAttributeMaxDynamicSharedMemorySize, SMEM_TOTAL);

    TapSpec te; te.n = 2;                 // even outputs l=2t: k=1 @ t, k=3 @ t-1
    te.widx[0] = 1; te.dt[0] = 0;
    te.widx[1] = 3; te.dt[1] = -1;
    for (int k = 2; k < 7; k++) { te.widx[k] = 0; te.dt[k] = 0; }
    TapSpec to; to.n = 2;                 // odd outputs l=2t+1: k=0 @ t+1, k=2 @ t
    to.widx[0] = 0; to.dt[0] = 1;
    to.widx[1] = 2; to.dt[1] = 0;
    for (int k = 2; k < 7; k++) { to.widx[k] = 0; to.dt[k] = 0; }
    TapSpec t7; t7.n = 7;
    for (int k = 0; k < 7; k++) { t7.widx[k] = k; t7.dt[k] = k - 3; }
    TapSpec tz; tz.n = 1;
    for (int k = 0; k < 7; k++) { tz.widx[k] = 0; tz.dt[k] = 0; }

    // 1: weight absmean partials
    absmean_part_all<<<dim3(256, 3), 256>>>(w_up, w_r1, w_r2, part);
    // 2: finalize scales
    absmean_fin_all<<<3, 256>>>(part, ws);
    // 3: pack upsample weight -> bf16 [k][co][ci]
    pack_up_k<<<C, C>>>(w_up, ws, wu);
    // 4: pack both refine weights
    pack_r_both_k<<<dim3(C, 2), C>>>(w_r1, w_r2, ws, w1, w2);
    // 5: act-quant input x (token-major (B,T,CIN))
    act_quant_k<<<BATCH * T_IN / 8, 256>>>(x, qx, asx, BATCH * T_IN);
    // 6: fused transposed conv (even+odd phases), pipelined HMMA
    conv_mma_kernel<<<dim3(T_IN / MTILE, C / NTILE, BATCH), 256, SMEM_TOTAL>>>(
        qx, asx, T_IN, wu, ws, b_up, nullptr, h, 2, 2, te, to, 0);
    // 7: quantize h
    act_quant_k<<<BATCH * L_OUT / 8, 256>>>(h, qh, ash, BATCH * L_OUT);
    // 8: refine conv 1 (+SiLU)
    conv_mma_kernel<<<dim3(L_OUT / MTILE, C / NTILE, BATCH), 256, SMEM_TOTAL>>>(
        qh, ash, L_OUT, w1, ws + 1, b_r1, nullptr, r, 1, 1, t7, tz, 1);
    // 9: quantize silu(r)
    act_quant_k<<<BATCH * L_OUT / 8, 256>>>(r, qr, asr, BATCH * L_OUT);
    // 10: refine conv 2 (+residual h)
    conv_mma_kernel<<<dim3(L_OUT / MTILE, C / NTILE, BATCH), 256, SMEM_TOTAL>>>(
        qr, asr, L_OUT, w2, ws + 2, b_r2, h, hs, 1, 1, t7, tz, 0);
    // 11: LayerNorm -> output (B, L, Cout) fp32
    ln_k<<<BATCH * L_OUT / 8, 256>>>(hs, ln_w, ln_b, out);
}